// round 13
// baseline (speedup 1.0000x reference)
#include <cuda_runtime.h>
#include <cuda_bf16.h>
#include <math.h>
#include <stdint.h>

// Problem constants
#define Bn   1024
#define Tn   512
#define Dn   64
#define Hn   256
#define G4   1024
#define MIDn 64
#define An   3

// CTA = 128 rows x 64 gate-cols, 256 threads (8 warps, warp tile 32x32).
// K=320 consumed in round-5 order: h chunks k0..255 (4 x k64), then x (k256..319).
// Chunk ch -> buffer ch&1 (x -> buf0). A buffers XOR-swizzled, pitch 128B.
#define ABUF   49152                    // per A buffer (3 planes x 128 rows x 128B)
#define NBUF   2
#define B_OFF  (NBUF*ABUF)              // 98304
#define BPITCH 640
#define SMEM_TOT (B_OFF + 3*64*BPITCH)  // 98304 + 122880 = 221184

// ---------------- device scratch (static, no allocation) ----------------
__device__ __nv_bfloat16 g_W[3][G4][320];          // [plane][gatecol][k] k0..255=h, 256..319=x
__device__ __nv_bfloat16 g_xT[3][Tn][Bn][Dn];      // split x, t-major
__device__ __nv_bfloat16 g_h[2][3][Bn][Hn];        // ping-pong split h
__device__ float g_br[G4];
__device__ float g_hfull[Bn*Hn];
__device__ float g_a1[Bn*MIDn];
__device__ float g_v1[Bn*MIDn];
__device__ int   g_bar4[32];                        // [bi][quarter] arrival counters

// ---------------- helpers ----------------
__device__ __forceinline__ void split3(float v, __nv_bfloat16& b1,
                                       __nv_bfloat16& b2, __nv_bfloat16& b3) {
    b1 = __float2bfloat16(v);
    float r = v - __bfloat162float(b1);
    b2 = __float2bfloat16(r);
    float r2 = r - __bfloat162float(b2);
    b3 = __float2bfloat16(r2);
}

__device__ __forceinline__ uint32_t smem_u32(const void* p) {
    uint32_t a;
    asm("{ .reg .u64 t; cvta.to.shared.u64 t, %1; cvt.u32.u64 %0, t; }" : "=r"(a) : "l"(p));
    return a;
}

__device__ __forceinline__ void cp16(uint32_t dst, const void* src) {
    asm volatile("cp.async.cg.shared.global [%0], [%1], 16;" :: "r"(dst), "l"(src) : "memory");
}
__device__ __forceinline__ void cp_commit() {
    asm volatile("cp.async.commit_group;" ::: "memory");
}

__device__ __forceinline__ int ld_acq(const int* p) {
    int v;
    asm volatile("ld.global.acquire.gpu.b32 %0, [%1];" : "=r"(v) : "l"(p) : "memory");
    return v;
}

#define LDSM4(R, addr) \
    asm volatile("ldmatrix.sync.aligned.m8n8.x4.shared.b16 {%0,%1,%2,%3}, [%4];" \
        : "=r"((R)[0]), "=r"((R)[1]), "=r"((R)[2]), "=r"((R)[3]) : "r"(addr))

__device__ __forceinline__ void mma_bf16(float c[4], const uint32_t a[4],
                                         uint32_t b0, uint32_t b1) {
    asm volatile(
        "mma.sync.aligned.m16n8k16.row.col.f32.bf16.bf16.f32 "
        "{%0,%1,%2,%3}, {%4,%5,%6,%7}, {%8,%9}, {%0,%1,%2,%3};"
        : "+f"(c[0]), "+f"(c[1]), "+f"(c[2]), "+f"(c[3])
        : "r"(a[0]), "r"(a[1]), "r"(a[2]), "r"(a[3]), "r"(b0), "r"(b1));
}

// ---------------- prep kernels ----------------
// k-space: k 0..255 = h units (Wc rows 64+k), k 256..319 = x dims (Wc rows k-256)
__global__ void wsplit_kernel(const float* __restrict__ Wc, const float* __restrict__ bc) {
    int idx = blockIdx.x * blockDim.x + threadIdx.x;
    if (idx < G4 * 320) {
        int k = idx % 320;
        int gcol = idx / 320;
        int u = gcol >> 2, g = gcol & 3;
        int r = (k < 256) ? (64 + k) : (k - 256);
        float w = Wc[r * G4 + g * Hn + u];
        __nv_bfloat16 s[3];
        split3(w, s[0], s[1], s[2]);
#pragma unroll
        for (int p = 0; p < 3; p++) g_W[p][gcol][k] = s[p];
    }
    if (idx < G4) {
        int u = idx >> 2, g = idx & 3;
        g_br[idx] = bc[g * Hn + u];
    }
}

__global__ void xsplit_kernel(const float* __restrict__ x) {
    int idx = blockIdx.x * blockDim.x + threadIdx.x;
    int d = idx & 63;
    int tt = (idx >> 6) & 511;
    int b = idx >> 15;
    if (b >= Bn) return;
    float v = x[((size_t)b * Tn + tt) * Dn + d];
    __nv_bfloat16 s[3];
    split3(v, s[0], s[1], s[2]);
#pragma unroll
    for (int p = 0; p < 3; p++) g_xT[p][tt][b][d] = s[p];
}

__global__ void init_kernel() {
    int idx = blockIdx.x * blockDim.x + threadIdx.x;
    if (idx < 3 * Bn * Hn / 2)
        ((unsigned*)g_h[0])[idx] = 0u;
    if (idx < 32) g_bar4[idx] = 0;
}

// ---------------- persistent step kernel ----------------
// grid (8, 16): bi = batch slice (128 rows), ci = 16 hidden units (64 gate cols)
__global__ __launch_bounds__(256)
void step_kernel() {
    extern __shared__ char dsm[];
    const uint32_t sbase = smem_u32(dsm);

    const int tid  = threadIdx.x;
    const int lane = tid & 31;
    const int warp = tid >> 5;
    const int wm = warp & 3;
    const int wn = warp >> 2;
    const int bi = blockIdx.x;
    const int ci = blockIdx.y;
    const int row0 = bi * 128;

    // resident B (weights, K=320): 3 planes x 64 cols x 640B, XOR-swizzled
#pragma unroll
    for (int i = 0; i < 30; i++) {
        int flat = i * 256 + tid;                 // < 7680
        int q = flat % 40;
        int n = (flat / 40) & 63;
        int p = flat / 2560;
        uint32_t off = (uint32_t)(q * 16) ^ (uint32_t)((n & 7) << 4);
        cp16(sbase + B_OFF + (uint32_t)(p * 64 + n) * BPITCH + off,
             (const char*)&g_W[p][ci * 64 + n][q * 8]);
    }
    cp_commit();

    float cold[8], nold[8];
#pragma unroll
    for (int q = 0; q < 8; q++) { cold[q] = 0.0f; nold[q] = 1.0f; }

    const int mrow = lane & 15;
    const int kAo  = (lane >> 4) << 3;
    const int nBo  = ((lane >> 4) << 3) + (lane & 7);
    const int kBo  = ((lane >> 3) & 1) << 3;
    const bool odd = lane & 1;
    const int jh = (lane >> 1) & 1;

    float cm[2][4][4], cl[2][4][4];

    // B fragment loader for k16-step ks of a chunk at byte offset bko
    auto load_b = [&](uint32_t bf[3][2][4], uint32_t bko, int ks) {
#pragma unroll
        for (int p = 0; p < 3; p++)
#pragma unroll
            for (int pr = 0; pr < 2; pr++) {
                int brow = wn * 32 + pr * 16 + nBo;
                uint32_t off = (bko + (uint32_t)((ks * 16 + kBo) * 2)) ^ (uint32_t)((brow & 7) << 4);
                LDSM4(bf[p][pr], sbase + B_OFF + (uint32_t)(p * 64 + brow) * BPITCH + off);
            }
    };

    // one k=64 chunk: 4 k16 steps, 6-product bf16x6 (cm: hi*hi; cl: low-order),
    // B fragments double-buffered one k16 step ahead
    auto do_chunk = [&](uint32_t abase, uint32_t bko) {
        uint32_t bfr[2][3][2][4];
        load_b(bfr[0], bko, 0);
#pragma unroll
        for (int ks = 0; ks < 4; ks++) {
            uint32_t a[3][2][4];
#pragma unroll
            for (int p = 0; p < 3; p++)
#pragma unroll
                for (int mi = 0; mi < 2; mi++) {
                    int arow = wm * 32 + mi * 16 + mrow;
                    uint32_t off = (uint32_t)((ks * 16 + kAo) * 2) ^ (uint32_t)((arow & 7) << 4);
                    LDSM4(a[p][mi], abase + (uint32_t)(p * 128 + arow) * 128 + off);
                }
            if (ks < 3) load_b(bfr[(ks + 1) & 1], bko, ks + 1);
            const uint32_t (*b)[2][4] = bfr[ks & 1];
#pragma unroll
            for (int mi = 0; mi < 2; mi++)
#pragma unroll
                for (int ni = 0; ni < 4; ni++) {
                    const int pr = ni >> 1, o = (ni & 1) * 2;
                    mma_bf16(cm[mi][ni], a[0][mi], b[0][pr][o], b[0][pr][o+1]); // hi*hi
                    mma_bf16(cl[mi][ni], a[0][mi], b[1][pr][o], b[1][pr][o+1]); // hi*mid
                    mma_bf16(cl[mi][ni], a[1][mi], b[0][pr][o], b[0][pr][o+1]); // mid*hi
                    mma_bf16(cl[mi][ni], a[0][mi], b[2][pr][o], b[2][pr][o+1]); // hi*lo
                    mma_bf16(cl[mi][ni], a[1][mi], b[1][pr][o], b[1][pr][o+1]); // mid*mid
                    mma_bf16(cl[mi][ni], a[2][mi], b[0][pr][o], b[0][pr][o+1]); // lo*hi
                }
        }
    };

    // x(t) load into buffer 0 (k 256..319) - issued after h chunk 2 is consumed
    auto issue_x = [&](int t) {
#pragma unroll
        for (int i = 0; i < 12; i++) {
            int flat = i * 256 + tid;             // < 3072
            int q = flat & 7;
            int m = (flat >> 3) & 127;
            int p = flat >> 10;
            uint32_t off = (uint32_t)(q * 16) ^ (uint32_t)((m & 7) << 4);
            cp16(sbase + (uint32_t)(p * 128 + m) * 128 + off,
                 (const char*)&g_xT[p][t][row0 + m][q * 8]);
        }
        cp_commit();
    };

    // h-chunk producer: chunk ch (k = ch*64..) -> buffer ch&1
    auto issue_h = [&](int ch, int hbuf) {
        const uint32_t abase = sbase + (uint32_t)(ch & 1) * ABUF;
#pragma unroll
        for (int i = 0; i < 12; i++) {
            int flat = i * 256 + tid;
            int q = flat & 7;
            int m = (flat >> 3) & 127;
            int p = flat >> 10;
            uint32_t off = (uint32_t)(q * 16) ^ (uint32_t)((m & 7) << 4);
            cp16(abase + (uint32_t)(p * 128 + m) * 128 + off,
                 (const char*)&g_h[hbuf][p][row0 + m][ch * 64 + q * 8]);
        }
        cp_commit();
    };

    // quarter barrier wait: h units [64q, 64q+64) of step t ready
    auto wait_q = [&](int q, int t) {
        const int tgt = 4 * t;
        const int* p = &g_bar4[bi * 4 + q];
        while (ld_acq(p) < tgt) { }
    };

    for (int t = 0; t < Tn; t++) {
        const int hbuf = t & 1;

#pragma unroll
        for (int mi = 0; mi < 2; mi++)
#pragma unroll
            for (int ni = 0; ni < 4; ni++)
#pragma unroll
                for (int q = 0; q < 4; q++) { cm[mi][ni][q] = 0.0f; cl[mi][ni][q] = 0.0f; }

        // producers for the first two h chunks
        wait_q(0, t);
        issue_h(0, hbuf);                          // -> buf0
        wait_q(1, t);
        issue_h(1, hbuf);                          // -> buf1

        // ---- 5 chunks: h0..h3 (k 0..255) then x (k 256..319), round-5 k-order ----
#pragma unroll 1
        for (int ch = 0; ch < 5; ch++) {
            if (ch < 4) asm volatile("cp.async.wait_group 1;" ::: "memory");
            else        asm volatile("cp.async.wait_group 0;" ::: "memory");
            __syncthreads();

            const uint32_t abase = sbase + (uint32_t)((ch == 4 ? 0 : (ch & 1))) * ABUF;
            do_chunk(abase, (uint32_t)(ch * 128));

            __syncthreads();                       // chunk reads done
            if (ch + 2 < 4) {
                wait_q(ch + 2, t);
                issue_h(ch + 2, hbuf);             // refill buffer just consumed
            } else if (ch == 2) {
                issue_x(t);                        // x -> buf0 (ch2 reads done)
            }
        }

        const bool last = (t == Tn - 1);

        // ---- epilogue (Hs stages in buf1; its last reads were ch3, fully synced) ----
        __syncthreads();                           // x-chunk (buf0) reads done everywhere
        __nv_bfloat16* Hs = (__nv_bfloat16*)(dsm + ABUF);   // [3][128][16]

#pragma unroll
        for (int mi = 0; mi < 2; mi++)
#pragma unroll
            for (int ni = 0; ni < 4; ni++) {
                int col = ci * 64 + wn * 32 + ni * 8 + (lane & 3) * 2;
                float b0 = g_br[col], b1 = g_br[col + 1];
                float q0 = (cm[mi][ni][0] + cl[mi][ni][0]) + b0;
                float q1 = (cm[mi][ni][1] + cl[mi][ni][1]) + b1;
                float q2 = (cm[mi][ni][2] + cl[mi][ni][2]) + b0;
                float q3 = (cm[mi][ni][3] + cl[mi][ni][3]) + b1;
                float s0 = __shfl_xor_sync(0xFFFFFFFFu, q0, 1);
                float s1 = __shfl_xor_sync(0xFFFFFFFFu, q1, 1);
                float s2 = __shfl_xor_sync(0xFFFFFFFFu, q2, 1);
                float s3 = __shfl_xor_sync(0xFFFFFFFFu, q3, 1);

                float gi = odd ? s2 : q0;
                float gf = odd ? s3 : q1;
                float go = odd ? q2 : s0;
                float gz = odd ? q3 : s1;

                const int row = wm * 32 + mi * 16 + (lane >> 2) + (odd ? 8 : 0);
                const int ul  = wn * 8 + ni * 2 + jh;
                const int qi  = mi * 4 + ni;

                gi = fminf(fmaxf(gi, -5.0f), 5.0f);
                gf = fminf(fmaxf(gf, -5.0f), 5.0f);
                float iv = __expf(gi);
                float fv = __expf(gf);

                float cv = fv * cold[qi] + iv * (1.0f - 2.0f / (__expf(2.0f * gz) + 1.0f));
                cv = fminf(fmaxf(cv, -1e6f), 1e6f);
                float nv = fv * nold[qi] + iv;
                nv = fminf(fmaxf(nv, 1e-6f), 1e6f);
                cold[qi] = cv;
                nold[qi] = nv;

                float ov = 1.0f / (1.0f + __expf(-go));
                float hv = ov * (cv / nv);
                if (!isfinite(hv)) hv = 0.0f;

                __nv_bfloat16 h1, h2, h3;
                split3(hv, h1, h2, h3);
                Hs[(0 * 128 + row) * 16 + ul] = h1;
                Hs[(1 * 128 + row) * 16 + ul] = h2;
                Hs[(2 * 128 + row) * 16 + ul] = h3;
                if (last) g_hfull[(row0 + row) * Hn + ci * 16 + ul] = hv;
            }
        __syncthreads();

        if (!last) {
            const int nbuf = hbuf ^ 1;
#pragma unroll
            for (int i = 0; i < 3; i++) {
                int flat = i * 256 + tid;
                int q = flat & 1;
                int m = (flat >> 1) & 127;
                int p = flat >> 8;
                uint4 v = *(const uint4*)&Hs[(p * 128 + m) * 16 + q * 8];
                *(uint4*)&g_h[nbuf][p][row0 + m][ci * 16 + q * 8] = v;
            }
            __threadfence();
            __syncthreads();                       // Hs reads done; h visible
            if (tid == 0) atomicAdd(&g_bar4[bi * 4 + (ci >> 2)], 1);
        }
    }
}

// ---------------- heads ----------------
__global__ void heads1_kernel(const float* __restrict__ Wa1, const float* __restrict__ ba1,
                              const float* __restrict__ Wv1, const float* __restrict__ bv1) {
    int idx = blockIdx.x * blockDim.x + threadIdx.x;
    if (idx >= Bn * 128) return;
    int b = idx >> 7;
    int j = idx & 127;
    const float* hrow = g_hfull + b * Hn;
    if (j < MIDn) {
        float s = ba1[j];
#pragma unroll 8
        for (int k = 0; k < Hn; k++) s = fmaf(hrow[k], Wa1[k * MIDn + j], s);
        g_a1[b * MIDn + j] = fmaxf(s, 0.0f);
    } else {
        int jj = j - MIDn;
        float s = bv1[jj];
#pragma unroll 8
        for (int k = 0; k < Hn; k++) s = fmaf(hrow[k], Wv1[k * MIDn + jj], s);
        g_v1[b * MIDn + jj] = fmaxf(s, 0.0f);
    }
}

__global__ void heads2_kernel(const float* __restrict__ Wa2, const float* __restrict__ ba2,
                              const float* __restrict__ Wv2, const float* __restrict__ bv2,
                              float* __restrict__ out) {
    int b = blockIdx.x * blockDim.x + threadIdx.x;
    if (b >= Bn) return;
    float l0 = ba2[0], l1 = ba2[1], l2 = ba2[2];
#pragma unroll 8
    for (int m = 0; m < MIDn; m++) {
        float a = g_a1[b * MIDn + m];
        l0 = fmaf(a, Wa2[m * An + 0], l0);
        l1 = fmaf(a, Wa2[m * An + 1], l1);
        l2 = fmaf(a, Wa2[m * An + 2], l2);
    }
    float mx = fmaxf(l0, fmaxf(l1, l2));
    float e0 = expf(l0 - mx), e1 = expf(l1 - mx), e2 = expf(l2 - mx);
    float s = e0 + e1 + e2;
    out[b * An + 0] = e0 / s;
    out[b * An + 1] = e1 / s;
    out[b * An + 2] = e2 / s;

    float v = bv2[0];
#pragma unroll 8
    for (int m = 0; m < MIDn; m++) v = fmaf(g_v1[b * MIDn + m], Wv2[m], v);
    out[Bn * An + b] = v;
}

// ---------------- launch ----------------
extern "C" void kernel_launch(void* const* d_in, const int* in_sizes, int n_in,
                              void* d_out, int out_size) {
    const float* x   = (const float*)d_in[0];
    const float* Wc  = (const float*)d_in[1];
    const float* bc  = (const float*)d_in[2];
    const float* Wa1 = (const float*)d_in[3];
    const float* ba1 = (const float*)d_in[4];
    const float* Wa2 = (const float*)d_in[5];
    const float* ba2 = (const float*)d_in[6];
    const float* Wv1 = (const float*)d_in[7];
    const float* bv1 = (const float*)d_in[8];
    const float* Wv2 = (const float*)d_in[9];
    const float* bv2 = (const float*)d_in[10];
    float* out = (float*)d_out;

    cudaFuncSetAttribute(step_kernel, cudaFuncAttributeMaxDynamicSharedMemorySize, SMEM_TOT);

    wsplit_kernel<<<(G4 * 320 + 255) / 256, 256>>>(Wc, bc);
    xsplit_kernel<<<(Bn * Tn * Dn + 255) / 256, 256>>>(x);
    init_kernel<<<(3 * Bn * Hn / 2 + 255) / 256, 256>>>();

    step_kernel<<<dim3(8, 16), 256, SMEM_TOT>>>();

    heads1_kernel<<<(Bn * 128 + 255) / 256, 256>>>(Wa1, ba1, Wv1, bv1);
    heads2_kernel<<<(Bn + 255) / 256, 256>>>(Wa2, ba2, Wv2, bv2, out);
}

// round 14
// speedup vs baseline: 1.0507x; 1.0507x over previous
#include <cuda_runtime.h>
#include <cuda_bf16.h>
#include <math.h>
#include <stdint.h>

// Problem constants
#define Bn   1024
#define Tn   512
#define Dn   64
#define Hn   256
#define G4   1024
#define MIDn 64
#define An   3

// CTA = 64 rows x 64 gate-cols, 128 threads (4 warps, warp tile 32x32).
// 2 CTAs per SM (anti-phase latency hiding). A and B both streamed per k64 chunk.
// Buffers: pair0 = {A0,B0}, pair1 = {A1,B1}; each 3 planes x 64 rows x 128B, XOR swizzle.
#define ABUF   24576
#define SMEM_TOT (4*ABUF)               // 98304

// ---------------- device scratch (static, no allocation) ----------------
__device__ __nv_bfloat16 g_W[3][G4][320];          // [plane][gatecol][k] k0..255=h, 256..319=x
__device__ __nv_bfloat16 g_xT[3][Tn][Bn][Dn];      // split x, t-major
__device__ __nv_bfloat16 g_h[2][3][Bn][Hn];        // ping-pong split h
__device__ float g_br[G4];
__device__ float g_hfull[Bn*Hn];
__device__ float g_a1[Bn*MIDn];
__device__ float g_v1[Bn*MIDn];
__device__ int   g_bar4[64];                        // [bi 0..15][quarter 0..3]

// ---------------- helpers ----------------
__device__ __forceinline__ void split3(float v, __nv_bfloat16& b1,
                                       __nv_bfloat16& b2, __nv_bfloat16& b3) {
    b1 = __float2bfloat16(v);
    float r = v - __bfloat162float(b1);
    b2 = __float2bfloat16(r);
    float r2 = r - __bfloat162float(b2);
    b3 = __float2bfloat16(r2);
}

__device__ __forceinline__ uint32_t smem_u32(const void* p) {
    uint32_t a;
    asm("{ .reg .u64 t; cvta.to.shared.u64 t, %1; cvt.u32.u64 %0, t; }" : "=r"(a) : "l"(p));
    return a;
}

__device__ __forceinline__ void cp16(uint32_t dst, const void* src) {
    asm volatile("cp.async.cg.shared.global [%0], [%1], 16;" :: "r"(dst), "l"(src) : "memory");
}
__device__ __forceinline__ void cp_commit() {
    asm volatile("cp.async.commit_group;" ::: "memory");
}

__device__ __forceinline__ int ld_acq(const int* p) {
    int v;
    asm volatile("ld.global.acquire.gpu.b32 %0, [%1];" : "=r"(v) : "l"(p) : "memory");
    return v;
}

#define LDSM4(R, addr) \
    asm volatile("ldmatrix.sync.aligned.m8n8.x4.shared.b16 {%0,%1,%2,%3}, [%4];" \
        : "=r"((R)[0]), "=r"((R)[1]), "=r"((R)[2]), "=r"((R)[3]) : "r"(addr))

__device__ __forceinline__ void mma_bf16(float c[4], const uint32_t a[4],
                                         uint32_t b0, uint32_t b1) {
    asm volatile(
        "mma.sync.aligned.m16n8k16.row.col.f32.bf16.bf16.f32 "
        "{%0,%1,%2,%3}, {%4,%5,%6,%7}, {%8,%9}, {%0,%1,%2,%3};"
        : "+f"(c[0]), "+f"(c[1]), "+f"(c[2]), "+f"(c[3])
        : "r"(a[0]), "r"(a[1]), "r"(a[2]), "r"(a[3]), "r"(b0), "r"(b1));
}

// ---------------- prep kernels ----------------
// k-space: k 0..255 = h units (Wc rows 64+k), k 256..319 = x dims (Wc rows k-256)
__global__ void wsplit_kernel(const float* __restrict__ Wc, const float* __restrict__ bc) {
    int idx = blockIdx.x * blockDim.x + threadIdx.x;
    if (idx < G4 * 320) {
        int k = idx % 320;
        int gcol = idx / 320;
        int u = gcol >> 2, g = gcol & 3;
        int r = (k < 256) ? (64 + k) : (k - 256);
        float w = Wc[r * G4 + g * Hn + u];
        __nv_bfloat16 s[3];
        split3(w, s[0], s[1], s[2]);
#pragma unroll
        for (int p = 0; p < 3; p++) g_W[p][gcol][k] = s[p];
    }
    if (idx < G4) {
        int u = idx >> 2, g = idx & 3;
        g_br[idx] = bc[g * Hn + u];
    }
}

__global__ void xsplit_kernel(const float* __restrict__ x) {
    int idx = blockIdx.x * blockDim.x + threadIdx.x;
    int d = idx & 63;
    int tt = (idx >> 6) & 511;
    int b = idx >> 15;
    if (b >= Bn) return;
    float v = x[((size_t)b * Tn + tt) * Dn + d];
    __nv_bfloat16 s[3];
    split3(v, s[0], s[1], s[2]);
#pragma unroll
    for (int p = 0; p < 3; p++) g_xT[p][tt][b][d] = s[p];
}

__global__ void init_kernel() {
    int idx = blockIdx.x * blockDim.x + threadIdx.x;
    if (idx < 3 * Bn * Hn / 2)
        ((unsigned*)g_h[0])[idx] = 0u;
    if (idx < 64) g_bar4[idx] = 0;
}

// ---------------- persistent step kernel ----------------
// grid (16, 16): bi = batch slice (64 rows), ci = 16 hidden units (64 gate cols)
__global__ __launch_bounds__(128, 2)
void step_kernel() {
    extern __shared__ char dsm[];
    const uint32_t sbase = smem_u32(dsm);

    const int tid  = threadIdx.x;
    const int lane = tid & 31;
    const int warp = tid >> 5;      // 0..3
    const int wm = warp & 1;
    const int wn = warp >> 1;
    const int bi = blockIdx.x;
    const int ci = blockIdx.y;
    const int row0 = bi * 64;

    float cold[8], nold[8];
#pragma unroll
    for (int q = 0; q < 8; q++) { cold[q] = 0.0f; nold[q] = 1.0f; }

    const int mrow = lane & 15;
    const int kAo  = (lane >> 4) << 3;
    const int nBo  = ((lane >> 4) << 3) + (lane & 7);
    const int kBo  = ((lane >> 3) & 1) << 3;
    const bool odd = lane & 1;
    const int jh = (lane >> 1) & 1;

    float cm[2][4][4], cl[2][4][4], cx[2][4][4];

    // one k=64 chunk from buffers at abase/bbase (each [3][64][128B], XOR swizzle)
    auto do_chunk = [&](uint32_t abase, uint32_t bbase) {
#pragma unroll
        for (int ks = 0; ks < 4; ks++) {
            uint32_t a[3][2][4], b[3][2][4];
#pragma unroll
            for (int p = 0; p < 3; p++) {
#pragma unroll
                for (int mi = 0; mi < 2; mi++) {
                    int arow = wm * 32 + mi * 16 + mrow;
                    uint32_t off = (uint32_t)((ks * 16 + kAo) * 2) ^ (uint32_t)((arow & 7) << 4);
                    LDSM4(a[p][mi], abase + (uint32_t)(p * 64 + arow) * 128 + off);
                }
#pragma unroll
                for (int pr = 0; pr < 2; pr++) {
                    int brow = wn * 32 + pr * 16 + nBo;
                    uint32_t off = (uint32_t)((ks * 16 + kBo) * 2) ^ (uint32_t)((brow & 7) << 4);
                    LDSM4(b[p][pr], bbase + (uint32_t)(p * 64 + brow) * 128 + off);
                }
            }
#pragma unroll
            for (int mi = 0; mi < 2; mi++)
#pragma unroll
                for (int ni = 0; ni < 4; ni++) {
                    const int pr = ni >> 1, o = (ni & 1) * 2;
                    mma_bf16(cm[mi][ni], a[0][mi], b[0][pr][o], b[0][pr][o+1]); // hi*hi
                    mma_bf16(cl[mi][ni], a[0][mi], b[1][pr][o], b[1][pr][o+1]); // hi*mid
                    mma_bf16(cl[mi][ni], a[1][mi], b[0][pr][o], b[0][pr][o+1]); // mid*hi
                    mma_bf16(cl[mi][ni], a[0][mi], b[2][pr][o], b[2][pr][o+1]); // hi*lo
                    mma_bf16(cl[mi][ni], a[1][mi], b[1][pr][o], b[1][pr][o+1]); // mid*mid
                    mma_bf16(cl[mi][ni], a[2][mi], b[0][pr][o], b[0][pr][o+1]); // lo*hi
                }
        }
    };

    // h-chunk ch (k = ch*64..): A from g_h, B from g_W -> buffer pair
    auto issue_h = [&](int ch, int hbuf, int pair) {
        const uint32_t abase = sbase + (uint32_t)pair * ABUF;
        const uint32_t bbase = sbase + (uint32_t)(2 + pair) * ABUF;
#pragma unroll
        for (int i = 0; i < 12; i++) {
            int flat = i * 128 + tid;             // < 1536
            int q = flat & 7;
            int m = (flat >> 3) & 63;
            int p = flat >> 9;
            uint32_t off = (uint32_t)(q * 16) ^ (uint32_t)((m & 7) << 4);
            cp16(abase + (uint32_t)(p * 64 + m) * 128 + off,
                 (const char*)&g_h[hbuf][p][row0 + m][ch * 64 + q * 8]);
        }
#pragma unroll
        for (int i = 0; i < 12; i++) {
            int flat = i * 128 + tid;
            int q = flat & 7;
            int n = (flat >> 3) & 63;
            int p = flat >> 9;
            uint32_t off = (uint32_t)(q * 16) ^ (uint32_t)((n & 7) << 4);
            cp16(bbase + (uint32_t)(p * 64 + n) * 128 + off,
                 (const char*)&g_W[p][ci * 64 + n][ch * 64 + q * 8]);
        }
        cp_commit();
    };

    // x chunk of step t (k 256..319) -> buffer pair
    auto issue_x = [&](int t, int pair) {
        const uint32_t abase = sbase + (uint32_t)pair * ABUF;
        const uint32_t bbase = sbase + (uint32_t)(2 + pair) * ABUF;
#pragma unroll
        for (int i = 0; i < 12; i++) {
            int flat = i * 128 + tid;
            int q = flat & 7;
            int m = (flat >> 3) & 63;
            int p = flat >> 9;
            uint32_t off = (uint32_t)(q * 16) ^ (uint32_t)((m & 7) << 4);
            cp16(abase + (uint32_t)(p * 64 + m) * 128 + off,
                 (const char*)&g_xT[p][t][row0 + m][q * 8]);
        }
#pragma unroll
        for (int i = 0; i < 12; i++) {
            int flat = i * 128 + tid;
            int q = flat & 7;
            int n = (flat >> 3) & 63;
            int p = flat >> 9;
            uint32_t off = (uint32_t)(q * 16) ^ (uint32_t)((n & 7) << 4);
            cp16(bbase + (uint32_t)(p * 64 + n) * 128 + off,
                 (const char*)&g_W[p][ci * 64 + n][256 + q * 8]);
        }
        cp_commit();
    };

    // quarter barrier wait: h units [64q, 64q+64) of step t ready (4 producer CTAs each)
    auto wait_q = [&](int q, int t) {
        const int tgt = 4 * t;
        const int* p = &g_bar4[bi * 4 + q];
        while (ld_acq(p) < tgt) { }
    };

    issue_x(0, 1);                                 // x(0) -> pair1

    for (int t = 0; t < Tn; t++) {
        const int hbuf = t & 1;
        const int xp = (t & 1) ^ 1;                // pair holding x(t)
        const int hp = xp ^ 1;                     // first h pair

#pragma unroll
        for (int mi = 0; mi < 2; mi++)
#pragma unroll
            for (int ni = 0; ni < 4; ni++)
#pragma unroll
                for (int q = 0; q < 4; q++) { cm[mi][ni][q] = 0.0f; cl[mi][ni][q] = 0.0f; }

        wait_q(0, t);
        issue_h(0, hbuf, hp);                      // h0 flies during x compute

        // ---- x phase (pending: {x(t), h0}) ----
        asm volatile("cp.async.wait_group 1;" ::: "memory");
        __syncthreads();
        do_chunk(sbase + (uint32_t)xp * ABUF, sbase + (uint32_t)(2 + xp) * ABUF);

        // collapse x part + bias into cx, reset cm/cl
#pragma unroll
        for (int mi = 0; mi < 2; mi++)
#pragma unroll
            for (int ni = 0; ni < 4; ni++) {
                int col = ci * 64 + wn * 32 + ni * 8 + (lane & 3) * 2;
                float b0 = g_br[col], b1 = g_br[col + 1];
                cx[mi][ni][0] = cm[mi][ni][0] + cl[mi][ni][0] + b0;
                cx[mi][ni][1] = cm[mi][ni][1] + cl[mi][ni][1] + b1;
                cx[mi][ni][2] = cm[mi][ni][2] + cl[mi][ni][2] + b0;
                cx[mi][ni][3] = cm[mi][ni][3] + cl[mi][ni][3] + b1;
#pragma unroll
                for (int q = 0; q < 4; q++) { cm[mi][ni][q] = 0.0f; cl[mi][ni][q] = 0.0f; }
            }

        __syncthreads();                           // pair xp reads done
        wait_q(1, t);
        issue_h(1, hbuf, xp);

        const bool last = (t == Tn - 1);

        // ---- h phase: chunks 0..3; h0->hp, h1->xp, h2->hp, h3->xp ----
#pragma unroll 1
        for (int ch = 0; ch < 4; ch++) {
            asm volatile("cp.async.wait_group 1;" ::: "memory");
            __syncthreads();

            const int pair = hp ^ (ch & 1);
            do_chunk(sbase + (uint32_t)pair * ABUF, sbase + (uint32_t)(2 + pair) * ABUF);

            __syncthreads();                       // chunk reads done
            if (ch == 0) { wait_q(2, t); issue_h(2, hbuf, hp); }
            else if (ch == 1) { wait_q(3, t); issue_h(3, hbuf, xp); }
            else if (ch == 2) { issue_x(last ? 0 : t + 1, hp); }  // pair hp free
        }
        // pending after loop: exactly {x(t+1)}

        // ---- epilogue (Hs stages in pair xp A-buffer: h3 consumed, x(t+1) is in hp) ----
        __nv_bfloat16* Hs = (__nv_bfloat16*)(dsm + xp * ABUF);   // [3][64][16]

#pragma unroll
        for (int mi = 0; mi < 2; mi++)
#pragma unroll
            for (int ni = 0; ni < 4; ni++) {
                float q0 = (cm[mi][ni][0] + cl[mi][ni][0]) + cx[mi][ni][0];
                float q1 = (cm[mi][ni][1] + cl[mi][ni][1]) + cx[mi][ni][1];
                float q2 = (cm[mi][ni][2] + cl[mi][ni][2]) + cx[mi][ni][2];
                float q3 = (cm[mi][ni][3] + cl[mi][ni][3]) + cx[mi][ni][3];
                float s0 = __shfl_xor_sync(0xFFFFFFFFu, q0, 1);
                float s1 = __shfl_xor_sync(0xFFFFFFFFu, q1, 1);
                float s2 = __shfl_xor_sync(0xFFFFFFFFu, q2, 1);
                float s3 = __shfl_xor_sync(0xFFFFFFFFu, q3, 1);

                float gi = odd ? s2 : q0;
                float gf = odd ? s3 : q1;
                float go = odd ? q2 : s0;
                float gz = odd ? q3 : s1;

                const int row = wm * 32 + mi * 16 + (lane >> 2) + (odd ? 8 : 0);
                const int ul  = wn * 8 + ni * 2 + jh;
                const int qi  = mi * 4 + ni;

                gi = fminf(fmaxf(gi, -5.0f), 5.0f);
                gf = fminf(fmaxf(gf, -5.0f), 5.0f);
                float iv = __expf(gi);
                float fv = __expf(gf);

                float cv = fv * cold[qi] + iv * (1.0f - 2.0f / (__expf(2.0f * gz) + 1.0f));
                cv = fminf(fmaxf(cv, -1e6f), 1e6f);
                float nv = fv * nold[qi] + iv;
                nv = fminf(fmaxf(nv, 1e-6f), 1e6f);
                cold[qi] = cv;
                nold[qi] = nv;

                float ov = 1.0f / (1.0f + __expf(-go));
                float hv = ov * (cv / nv);
                if (!isfinite(hv)) hv = 0.0f;

                __nv_bfloat16 h1, h2, h3;
                split3(hv, h1, h2, h3);
                Hs[(0 * 64 + row) * 16 + ul] = h1;
                Hs[(1 * 64 + row) * 16 + ul] = h2;
                Hs[(2 * 64 + row) * 16 + ul] = h3;
                if (last) g_hfull[(row0 + row) * Hn + ci * 16 + ul] = hv;
            }
        __syncthreads();

        if (!last) {
            const int nbuf = hbuf ^ 1;
#pragma unroll
            for (int i = 0; i < 3; i++) {
                int flat = i * 128 + tid;          // < 384
                int q = flat & 1;
                int m = (flat >> 1) & 63;
                int p = flat >> 7;
                uint4 v = *(const uint4*)&Hs[(p * 64 + m) * 16 + q * 8];
                *(uint4*)&g_h[nbuf][p][row0 + m][ci * 16 + q * 8] = v;
            }
            __threadfence();
            __syncthreads();                       // Hs reads done; h visible
            if (tid == 0) atomicAdd(&g_bar4[bi * 4 + (ci >> 2)], 1);
        }
    }
}

// ---------------- heads ----------------
__global__ void heads1_kernel(const float* __restrict__ Wa1, const float* __restrict__ ba1,
                              const float* __restrict__ Wv1, const float* __restrict__ bv1) {
    int idx = blockIdx.x * blockDim.x + threadIdx.x;
    if (idx >= Bn * 128) return;
    int b = idx >> 7;
    int j = idx & 127;
    const float* hrow = g_hfull + b * Hn;
    if (j < MIDn) {
        float s = ba1[j];
#pragma unroll 8
        for (int k = 0; k < Hn; k++) s = fmaf(hrow[k], Wa1[k * MIDn + j], s);
        g_a1[b * MIDn + j] = fmaxf(s, 0.0f);
    } else {
        int jj = j - MIDn;
        float s = bv1[jj];
#pragma unroll 8
        for (int k = 0; k < Hn; k++) s = fmaf(hrow[k], Wv1[k * MIDn + jj], s);
        g_v1[b * MIDn + jj] = fmaxf(s, 0.0f);
    }
}

__global__ void heads2_kernel(const float* __restrict__ Wa2, const float* __restrict__ ba2,
                              const float* __restrict__ Wv2, const float* __restrict__ bv2,
                              float* __restrict__ out) {
    int b = blockIdx.x * blockDim.x + threadIdx.x;
    if (b >= Bn) return;
    float l0 = ba2[0], l1 = ba2[1], l2 = ba2[2];
#pragma unroll 8
    for (int m = 0; m < MIDn; m++) {
        float a = g_a1[b * MIDn + m];
        l0 = fmaf(a, Wa2[m * An + 0], l0);
        l1 = fmaf(a, Wa2[m * An + 1], l1);
        l2 = fmaf(a, Wa2[m * An + 2], l2);
    }
    float mx = fmaxf(l0, fmaxf(l1, l2));
    float e0 = expf(l0 - mx), e1 = expf(l1 - mx), e2 = expf(l2 - mx);
    float s = e0 + e1 + e2;
    out[b * An + 0] = e0 / s;
    out[b * An + 1] = e1 / s;
    out[b * An + 2] = e2 / s;

    float v = bv2[0];
#pragma unroll 8
    for (int m = 0; m < MIDn; m++) v = fmaf(g_v1[b * MIDn + m], Wv2[m], v);
    out[Bn * An + b] = v;
}

// ---------------- launch ----------------
extern "C" void kernel_launch(void* const* d_in, const int* in_sizes, int n_in,
                              void* d_out, int out_size) {
    const float* x   = (const float*)d_in[0];
    const float* Wc  = (const float*)d_in[1];
    const float* bc  = (const float*)d_in[2];
    const float* Wa1 = (const float*)d_in[3];
    const float* ba1 = (const float*)d_in[4];
    const float* Wa2 = (const float*)d_in[5];
    const float* ba2 = (const float*)d_in[6];
    const float* Wv1 = (const float*)d_in[7];
    const float* bv1 = (const float*)d_in[8];
    const float* Wv2 = (const float*)d_in[9];
    const float* bv2 = (const float*)d_in[10];
    float* out = (float*)d_out;

    cudaFuncSetAttribute(step_kernel, cudaFuncAttributeMaxDynamicSharedMemorySize, SMEM_TOT);

    wsplit_kernel<<<(G4 * 320 + 255) / 256, 256>>>(Wc, bc);
    xsplit_kernel<<<(Bn * Tn * Dn + 255) / 256, 256>>>(x);
    init_kernel<<<(3 * Bn * Hn / 2 + 255) / 256, 256>>>();

    step_kernel<<<dim3(16, 16), 128, SMEM_TOT>>>();

    heads1_kernel<<<(Bn * 128 + 255) / 256, 256>>>(Wa1, ba1, Wv1, bv1);
    heads2_kernel<<<(Bn + 255) / 256, 256>>>(Wa2, ba2, Wv2, bv2, out);
}

// round 16
// speedup vs baseline: 1.0936x; 1.0408x over previous
#include <cuda_runtime.h>
#include <cuda_bf16.h>
#include <math.h>
#include <stdint.h>

// Problem constants
#define Bn   1024
#define Tn   512
#define Dn   64
#define Hn   256
#define G4   1024
#define MIDn 64
#define An   3

// CTA = 128 rows x 64 gate-cols, 256 threads (8 warps, warp tile 32x32).
// Warp-pair p = {warp p, warp p+4} owns rows [32p,32p+32) and 2 private A buffers.
// No CTA-wide syncs in the step loop; pairs sync via named barrier (1+p, 64).
#define PBUF   12288                    // per-pair A buffer (3 planes x 32 rows x 128B)
#define B_OFF  (4*2*PBUF)               // 98304
#define BPITCH 640
#define SMEM_TOT (B_OFF + 3*64*BPITCH)  // 98304 + 122880 = 221184

// ---------------- device scratch (static, no allocation) ----------------
__device__ __nv_bfloat16 g_W[3][G4][320];          // [plane][gatecol][k] k0..255=h, 256..319=x
__device__ __nv_bfloat16 g_xT[3][Tn][Bn][Dn];      // split x, t-major
__device__ __nv_bfloat16 g_h[2][3][Bn][Hn];        // ping-pong split h
__device__ float g_br[G4];
__device__ float g_hfull[Bn*Hn];
__device__ float g_a1[Bn*MIDn];
__device__ float g_v1[Bn*MIDn];
__device__ int   g_bar4[32];                        // [bi][quarter], counts pair-arrivals

// ---------------- helpers ----------------
__device__ __forceinline__ void split3(float v, __nv_bfloat16& b1,
                                       __nv_bfloat16& b2, __nv_bfloat16& b3) {
    b1 = __float2bfloat16(v);
    float r = v - __bfloat162float(b1);
    b2 = __float2bfloat16(r);
    float r2 = r - __bfloat162float(b2);
    b3 = __float2bfloat16(r2);
}

__device__ __forceinline__ uint32_t smem_u32(const void* p) {
    uint32_t a;
    asm("{ .reg .u64 t; cvta.to.shared.u64 t, %1; cvt.u32.u64 %0, t; }" : "=r"(a) : "l"(p));
    return a;
}

__device__ __forceinline__ void cp16(uint32_t dst, const void* src) {
    asm volatile("cp.async.cg.shared.global [%0], [%1], 16;" :: "r"(dst), "l"(src) : "memory");
}
__device__ __forceinline__ void cp_commit() {
    asm volatile("cp.async.commit_group;" ::: "memory");
}

__device__ __forceinline__ int ld_acq(const int* p) {
    int v;
    asm volatile("ld.global.acquire.gpu.b32 %0, [%1];" : "=r"(v) : "l"(p) : "memory");
    return v;
}

#define LDSM4(R, addr) \
    asm volatile("ldmatrix.sync.aligned.m8n8.x4.shared.b16 {%0,%1,%2,%3}, [%4];" \
        : "=r"((R)[0]), "=r"((R)[1]), "=r"((R)[2]), "=r"((R)[3]) : "r"(addr))

__device__ __forceinline__ void mma_bf16(float c[4], const uint32_t a[4],
                                         uint32_t b0, uint32_t b1) {
    asm volatile(
        "mma.sync.aligned.m16n8k16.row.col.f32.bf16.bf16.f32 "
        "{%0,%1,%2,%3}, {%4,%5,%6,%7}, {%8,%9}, {%0,%1,%2,%3};"
        : "+f"(c[0]), "+f"(c[1]), "+f"(c[2]), "+f"(c[3])
        : "r"(a[0]), "r"(a[1]), "r"(a[2]), "r"(a[3]), "r"(b0), "r"(b1));
}

// ---------------- prep kernels ----------------
// k-space: k 0..255 = h units (Wc rows 64+k), k 256..319 = x dims (Wc rows k-256)
__global__ void wsplit_kernel(const float* __restrict__ Wc, const float* __restrict__ bc) {
    int idx = blockIdx.x * blockDim.x + threadIdx.x;
    if (idx < G4 * 320) {
        int k = idx % 320;
        int gcol = idx / 320;
        int u = gcol >> 2, g = gcol & 3;
        int r = (k < 256) ? (64 + k) : (k - 256);
        float w = Wc[r * G4 + g * Hn + u];
        __nv_bfloat16 s[3];
        split3(w, s[0], s[1], s[2]);
#pragma unroll
        for (int p = 0; p < 3; p++) g_W[p][gcol][k] = s[p];
    }
    if (idx < G4) {
        int u = idx >> 2, g = idx & 3;
        g_br[idx] = bc[g * Hn + u];
    }
}

__global__ void xsplit_kernel(const float* __restrict__ x) {
    int idx = blockIdx.x * blockDim.x + threadIdx.x;
    int d = idx & 63;
    int tt = (idx >> 6) & 511;
    int b = idx >> 15;
    if (b >= Bn) return;
    float v = x[((size_t)b * Tn + tt) * Dn + d];
    __nv_bfloat16 s[3];
    split3(v, s[0], s[1], s[2]);
#pragma unroll
    for (int p = 0; p < 3; p++) g_xT[p][tt][b][d] = s[p];
}

__global__ void init_kernel() {
    int idx = blockIdx.x * blockDim.x + threadIdx.x;
    if (idx < 3 * Bn * Hn / 2)
        ((unsigned*)g_h[0])[idx] = 0u;
    if (idx < 32) g_bar4[idx] = 0;
}

// ---------------- persistent step kernel ----------------
// grid (8, 16): bi = batch slice (128 rows), ci = 16 hidden units (64 gate cols)
__global__ __launch_bounds__(256)
void step_kernel() {
    extern __shared__ char dsm[];
    const uint32_t sbase = smem_u32(dsm);

    const int tid  = threadIdx.x;
    const int lane = tid & 31;
    const int warp = tid >> 5;
    const int wm = warp & 3;        // pair id p
    const int wn = warp >> 2;       // 0/1 within pair
    const int p  = wm;
    const int ptid = (wn << 5) | lane;      // 0..63 within pair
    const int bi = blockIdx.x;
    const int ci = blockIdx.y;
    const int row0 = bi * 128;
    const int prow0 = row0 + p * 32;        // this pair's global row base

    const uint32_t PA0 = sbase + (uint32_t)(p * 2) * PBUF;
    const uint32_t PA1 = PA0 + PBUF;

#define BARP() asm volatile("bar.sync %0, 64;" :: "r"(1 + p) : "memory")

    // resident B (weights, K=320): 3 planes x 64 cols x 640B, XOR-swizzled (CTA-wide)
#pragma unroll
    for (int i = 0; i < 30; i++) {
        int flat = i * 256 + tid;                 // < 7680
        int q = flat % 40;
        int n = (flat / 40) & 63;
        int pp = flat / 2560;
        uint32_t off = (uint32_t)(q * 16) ^ (uint32_t)((n & 7) << 4);
        cp16(sbase + B_OFF + (uint32_t)(pp * 64 + n) * BPITCH + off,
             (const char*)&g_W[pp][ci * 64 + n][q * 8]);
    }
    cp_commit();

    float cold[8], nold[8];
#pragma unroll
    for (int q = 0; q < 8; q++) { cold[q] = 0.0f; nold[q] = 1.0f; }

    const int mrow = lane & 15;
    const int kAo  = (lane >> 4) << 3;
    const int nBo  = ((lane >> 4) << 3) + (lane & 7);
    const int kBo  = ((lane >> 3) & 1) << 3;
    const bool odd = lane & 1;
    const int jh = (lane >> 1) & 1;

    float cm[2][4][4], cl[2][4][4], cx[2][4][4];

    // one k=64 chunk from pair A buffer abuf + resident B at k-byte offset bko
    auto do_chunk = [&](uint32_t abuf, uint32_t bko) {
#pragma unroll
        for (int ks = 0; ks < 4; ks++) {
            uint32_t a[3][2][4], b[3][2][4];
#pragma unroll
            for (int pp = 0; pp < 3; pp++) {
#pragma unroll
                for (int mi = 0; mi < 2; mi++) {
                    int lr = mi * 16 + mrow;      // 0..31 within pair rows
                    uint32_t off = (uint32_t)((ks * 16 + kAo) * 2) ^ (uint32_t)((lr & 7) << 4);
                    LDSM4(a[pp][mi], abuf + (uint32_t)(pp * 32 + lr) * 128 + off);
                }
#pragma unroll
                for (int pr = 0; pr < 2; pr++) {
                    int brow = wn * 32 + pr * 16 + nBo;
                    uint32_t off = (bko + (uint32_t)((ks * 16 + kBo) * 2)) ^ (uint32_t)((brow & 7) << 4);
                    LDSM4(b[pp][pr], sbase + B_OFF + (uint32_t)(pp * 64 + brow) * BPITCH + off);
                }
            }
#pragma unroll
            for (int mi = 0; mi < 2; mi++)
#pragma unroll
                for (int ni = 0; ni < 4; ni++) {
                    const int pr = ni >> 1, o = (ni & 1) * 2;
                    mma_bf16(cm[mi][ni], a[0][mi], b[0][pr][o], b[0][pr][o+1]); // hi*hi
                    mma_bf16(cl[mi][ni], a[0][mi], b[1][pr][o], b[1][pr][o+1]); // hi*mid
                    mma_bf16(cl[mi][ni], a[1][mi], b[0][pr][o], b[0][pr][o+1]); // mid*hi
                    mma_bf16(cl[mi][ni], a[0][mi], b[2][pr][o], b[2][pr][o+1]); // hi*lo
                    mma_bf16(cl[mi][ni], a[1][mi], b[1][pr][o], b[1][pr][o+1]); // mid*mid
                    mma_bf16(cl[mi][ni], a[2][mi], b[0][pr][o], b[0][pr][o+1]); // lo*hi
                }
        }
    };

    // pair-local h-chunk copy: chunk ch (k = ch*64..) -> buffer (ch&1)
    auto issue_h = [&](int ch, int hbuf) {
        const uint32_t abuf = (ch & 1) ? PA1 : PA0;
#pragma unroll
        for (int i = 0; i < 12; i++) {
            int flat = i * 64 + ptid;             // < 768
            int q = flat & 7;
            int r = (flat >> 3) & 31;
            int pp = flat >> 8;
            uint32_t off = (uint32_t)(q * 16) ^ (uint32_t)((r & 7) << 4);
            cp16(abuf + (uint32_t)(pp * 32 + r) * 128 + off,
                 (const char*)&g_h[hbuf][pp][prow0 + r][ch * 64 + q * 8]);
        }
        cp_commit();
    };

    // pair-local x(t) copy into buffer 1 (k 256..319)
    auto issue_x = [&](int t) {
#pragma unroll
        for (int i = 0; i < 12; i++) {
            int flat = i * 64 + ptid;
            int q = flat & 7;
            int r = (flat >> 3) & 31;
            int pp = flat >> 8;
            uint32_t off = (uint32_t)(q * 16) ^ (uint32_t)((r & 7) << 4);
            cp16(PA1 + (uint32_t)(pp * 32 + r) * 128 + off,
                 (const char*)&g_xT[pp][t][prow0 + r][q * 8]);
        }
        cp_commit();
    };

    // quarter barrier wait: h units [64q, 64q+64) of step t ready
    // (4 producer CTAs x 4 pairs = 16 pair-arrivals per step)
    auto wait_q = [&](int q, int t) {
        const int tgt = 16 * t;
        const int* pc = &g_bar4[bi * 4 + q];
        while (ld_acq(pc) < tgt) { }
    };

    issue_x(0);                                    // pending: {B, x}
    asm volatile("cp.async.wait_group 0;" ::: "memory");
    __syncthreads();                               // B + x(0) visible CTA-wide

    for (int t = 0; t < Tn; t++) {
        const int hbuf = t & 1;
        const bool last = (t == Tn - 1);

#pragma unroll
        for (int mi = 0; mi < 2; mi++)
#pragma unroll
            for (int ni = 0; ni < 4; ni++)
#pragma unroll
                for (int q = 0; q < 4; q++) { cm[mi][ni][q] = 0.0f; cl[mi][ni][q] = 0.0f; }

        // ---- x phase: h0 copy flies during x compute ----
        wait_q(0, t);
        issue_h(0, hbuf);                          // -> PA0
        // pending here: {x(t), h0} at t>0 (x committed last step), {h0} at t=0
        asm volatile("cp.async.wait_group 1;" ::: "memory");   // x(t) retired
        BARP();                                    // pair's x copies visible
        do_chunk(PA1, 512u);                       // x part (k 256..319)

        // collapse x part + bias into cx, reset cm/cl
#pragma unroll
        for (int mi = 0; mi < 2; mi++)
#pragma unroll
            for (int ni = 0; ni < 4; ni++) {
                int col = ci * 64 + wn * 32 + ni * 8 + (lane & 3) * 2;
                float b0 = g_br[col], b1 = g_br[col + 1];
                cx[mi][ni][0] = cm[mi][ni][0] + cl[mi][ni][0] + b0;
                cx[mi][ni][1] = cm[mi][ni][1] + cl[mi][ni][1] + b1;
                cx[mi][ni][2] = cm[mi][ni][2] + cl[mi][ni][2] + b0;
                cx[mi][ni][3] = cm[mi][ni][3] + cl[mi][ni][3] + b1;
#pragma unroll
                for (int q = 0; q < 4; q++) { cm[mi][ni][q] = 0.0f; cl[mi][ni][q] = 0.0f; }
            }

        BARP();                                    // pair done reading PA1 (x)
        wait_q(1, t);
        issue_h(1, hbuf);                          // -> PA1; pending: {h0, h1}

        // ---- h phase: 4 chunks k=64, pair-local ping-pong ----
#pragma unroll 1
        for (int ch = 0; ch < 4; ch++) {
            if (ch == 3) asm volatile("cp.async.wait_group 0;" ::: "memory");
            else         asm volatile("cp.async.wait_group 1;" ::: "memory");
            BARP();

            do_chunk((ch & 1) ? PA1 : PA0, (uint32_t)(ch * 128));

            BARP();                                // pair done reading this buffer
            if (ch == 0)      { wait_q(2, t); issue_h(2, hbuf); }
            else if (ch == 1) { wait_q(3, t); issue_h(3, hbuf); }
        }
        if (!last) issue_x(t + 1);                 // PA1 free (h3 consumed, post-BARP)

        // ---- epilogue: pair-local, Hs staged in PA0 (h2 consumed, fully bar'd) ----
        __nv_bfloat16* Hs = (__nv_bfloat16*)(dsm + (size_t)(p * 2) * PBUF);

#pragma unroll
        for (int mi = 0; mi < 2; mi++)
#pragma unroll
            for (int ni = 0; ni < 4; ni++) {
                float q0 = (cm[mi][ni][0] + cl[mi][ni][0]) + cx[mi][ni][0];
                float q1 = (cm[mi][ni][1] + cl[mi][ni][1]) + cx[mi][ni][1];
                float q2 = (cm[mi][ni][2] + cl[mi][ni][2]) + cx[mi][ni][2];
                float q3 = (cm[mi][ni][3] + cl[mi][ni][3]) + cx[mi][ni][3];
                float s0 = __shfl_xor_sync(0xFFFFFFFFu, q0, 1);
                float s1 = __shfl_xor_sync(0xFFFFFFFFu, q1, 1);
                float s2 = __shfl_xor_sync(0xFFFFFFFFu, q2, 1);
                float s3 = __shfl_xor_sync(0xFFFFFFFFu, q3, 1);

                float gi = odd ? s2 : q0;
                float gf = odd ? s3 : q1;
                float go = odd ? q2 : s0;
                float gz = odd ? q3 : s1;

                const int lr = mi * 16 + (lane >> 2) + (odd ? 8 : 0);   // 0..31
                const int ul = wn * 8 + ni * 2 + jh;                     // 0..15
                const int qi = mi * 4 + ni;

                gi = fminf(fmaxf(gi, -5.0f), 5.0f);
                gf = fminf(fmaxf(gf, -5.0f), 5.0f);
                float iv = __expf(gi);
                float fv = __expf(gf);

                float cv = fv * cold[qi] + iv * (1.0f - 2.0f / (__expf(2.0f * gz) + 1.0f));
                cv = fminf(fmaxf(cv, -1e6f), 1e6f);
                float nv = fv * nold[qi] + iv;
                nv = fminf(fmaxf(nv, 1e-6f), 1e6f);
                cold[qi] = cv;
                nold[qi] = nv;

                float ov = 1.0f / (1.0f + __expf(-go));
                float hv = ov * (cv / nv);
                if (!isfinite(hv)) hv = 0.0f;

                __nv_bfloat16 h1, h2, h3;
                split3(hv, h1, h2, h3);
                Hs[(0 * 32 + lr) * 16 + ul] = h1;
                Hs[(1 * 32 + lr) * 16 + ul] = h2;
                Hs[(2 * 32 + lr) * 16 + ul] = h3;
                if (last) g_hfull[(prow0 + lr) * Hn + ci * 16 + ul] = hv;
            }
        BARP();                                    // Hs complete within pair

        if (!last) {
            const int nbuf = hbuf ^ 1;
#pragma unroll
            for (int i = 0; i < 3; i++) {
                int flat = i * 64 + ptid;          // < 192
                int q = flat & 1;
                int r = (flat >> 1) & 31;
                int pp = flat >> 6;
                uint4 v = *(const uint4*)&Hs[(pp * 32 + r) * 16 + q * 8];
                *(uint4*)&g_h[nbuf][pp][prow0 + r][ci * 16 + q * 8] = v;
            }
            __threadfence();
            BARP();                                // pair writes done & visible
            if (ptid == 0) atomicAdd(&g_bar4[bi * 4 + (ci >> 2)], 1);
        }
    }
#undef BARP
}

// ---------------- heads ----------------
__global__ void heads1_kernel(const float* __restrict__ Wa1, const float* __restrict__ ba1,
                              const float* __restrict__ Wv1, const float* __restrict__ bv1) {
    int idx = blockIdx.x * blockDim.x + threadIdx.x;
    if (idx >= Bn * 128) return;
    int b = idx >> 7;
    int j = idx & 127;
    const float* hrow = g_hfull + b * Hn;
    if (j < MIDn) {
        float s = ba1[j];
#pragma unroll 8
        for (int k = 0; k < Hn; k++) s = fmaf(hrow[k], Wa1[k * MIDn + j], s);
        g_a1[b * MIDn + j] = fmaxf(s, 0.0f);
    } else {
        int jj = j - MIDn;
        float s = bv1[jj];
#pragma unroll 8
        for (int k = 0; k < Hn; k++) s = fmaf(hrow[k], Wv1[k * MIDn + jj], s);
        g_v1[b * MIDn + jj] = fmaxf(s, 0.0f);
    }
}

__global__ void heads2_kernel(const float* __restrict__ Wa2, const float* __restrict__ ba2,
                              const float* __restrict__ Wv2, const float* __restrict__ bv2,
                              float* __restrict__ out) {
    int b = blockIdx.x * blockDim.x + threadIdx.x;
    if (b >= Bn) return;
    float l0 = ba2[0], l1 = ba2[1], l2 = ba2[2];
#pragma unroll 8
    for (int m = 0; m < MIDn; m++) {
        float a = g_a1[b * MIDn + m];
        l0 = fmaf(a, Wa2[m * An + 0], l0);
        l1 = fmaf(a, Wa2[m * An + 1], l1);
        l2 = fmaf(a, Wa2[m * An + 2], l2);
    }
    float mx = fmaxf(l0, fmaxf(l1, l2));
    float e0 = expf(l0 - mx), e1 = expf(l1 - mx), e2 = expf(l2 - mx);
    float s = e0 + e1 + e2;
    out[b * An + 0] = e0 / s;
    out[b * An + 1] = e1 / s;
    out[b * An + 2] = e2 / s;

    float v = bv2[0];
#pragma unroll 8
    for (int m = 0; m < MIDn; m++) v = fmaf(g_v1[b * MIDn + m], Wv2[m], v);
    out[Bn * An + b] = v;
}

// ---------------- launch ----------------
extern "C" void kernel_launch(void* const* d_in, const int* in_sizes, int n_in,
                              void* d_out, int out_size) {
    const float* x   = (const float*)d_in[0];
    const float* Wc  = (const float*)d_in[1];
    const float* bc  = (const float*)d_in[2];
    const float* Wa1 = (const float*)d_in[3];
    const float* ba1 = (const float*)d_in[4];
    const float* Wa2 = (const float*)d_in[5];
    const float* ba2 = (const float*)d_in[6];
    const float* Wv1 = (const float*)d_in[7];
    const float* bv1 = (const float*)d_in[8];
    const float* Wv2 = (const float*)d_in[9];
    const float* bv2 = (const float*)d_in[10];
    float* out = (float*)d_out;

    cudaFuncSetAttribute(step_kernel, cudaFuncAttributeMaxDynamicSharedMemorySize, SMEM_TOT);

    wsplit_kernel<<<(G4 * 320 + 255) / 256, 256>>>(Wc, bc);
    xsplit_kernel<<<(Bn * Tn * Dn + 255) / 256, 256>>>(x);
    init_kernel<<<(3 * Bn * Hn / 2 + 255) / 256, 256>>>();

    step_kernel<<<dim3(8, 16), 256, SMEM_TOT>>>();

    heads1_kernel<<<(Bn * 128 + 255) / 256, 256>>>(Wa1, ba1, Wv1, bv1);
    heads2_kernel<<<(Bn + 255) / 256, 256>>>(Wa2, ba2, Wv2, bv2, out);
}

// round 17
// speedup vs baseline: 1.1719x; 1.0716x over previous
#include <cuda_runtime.h>
#include <cuda_bf16.h>
#include <math.h>
#include <stdint.h>

// Problem constants
#define Bn   1024
#define Tn   512
#define Dn   64
#define Hn   256
#define G4   1024
#define MIDn 64
#define An   3

// CTA = 128 rows x 64 gate-cols, 256 threads (8 warps, warp tile 32x32).
// Warp-pair p = {warp 2p, warp 2p+1} owns rows [32p,32p+32) and 2 private A buffers.
// Pairs map across SMSPs so each SMSP hosts warps of TWO different pairs (anti-phase).
// No CTA-wide syncs in the step loop; pairs sync via named barrier (1+p, 64).
#define PBUF   12288                    // per-pair A buffer (3 planes x 32 rows x 128B)
#define B_OFF  (4*2*PBUF)               // 98304
#define BPITCH 640
#define SMEM_TOT (B_OFF + 3*64*BPITCH)  // 98304 + 122880 = 221184

// ---------------- device scratch (static, no allocation) ----------------
__device__ __nv_bfloat16 g_W[3][G4][320];          // [plane][gatecol][k] k0..255=h, 256..319=x
__device__ __nv_bfloat16 g_xT[3][Tn][Bn][Dn];      // split x, t-major
__device__ __nv_bfloat16 g_h[2][3][Bn][Hn];        // ping-pong split h
__device__ float g_br[G4];
__device__ float g_hfull[Bn*Hn];
__device__ float g_a1[Bn*MIDn];
__device__ float g_v1[Bn*MIDn];
__device__ int   g_bar4[32];                        // [bi][quarter], counts pair-arrivals

// ---------------- helpers ----------------
__device__ __forceinline__ void split3(float v, __nv_bfloat16& b1,
                                       __nv_bfloat16& b2, __nv_bfloat16& b3) {
    b1 = __float2bfloat16(v);
    float r = v - __bfloat162float(b1);
    b2 = __float2bfloat16(r);
    float r2 = r - __bfloat162float(b2);
    b3 = __float2bfloat16(r2);
}

__device__ __forceinline__ uint32_t smem_u32(const void* p) {
    uint32_t a;
    asm("{ .reg .u64 t; cvta.to.shared.u64 t, %1; cvt.u32.u64 %0, t; }" : "=r"(a) : "l"(p));
    return a;
}

__device__ __forceinline__ void cp16(uint32_t dst, const void* src) {
    asm volatile("cp.async.cg.shared.global [%0], [%1], 16;" :: "r"(dst), "l"(src) : "memory");
}
__device__ __forceinline__ void cp_commit() {
    asm volatile("cp.async.commit_group;" ::: "memory");
}

__device__ __forceinline__ int ld_acq(const int* p) {
    int v;
    asm volatile("ld.global.acquire.gpu.b32 %0, [%1];" : "=r"(v) : "l"(p) : "memory");
    return v;
}

#define LDSM4(R, addr) \
    asm volatile("ldmatrix.sync.aligned.m8n8.x4.shared.b16 {%0,%1,%2,%3}, [%4];" \
        : "=r"((R)[0]), "=r"((R)[1]), "=r"((R)[2]), "=r"((R)[3]) : "r"(addr))

__device__ __forceinline__ void mma_bf16(float c[4], const uint32_t a[4],
                                         uint32_t b0, uint32_t b1) {
    asm volatile(
        "mma.sync.aligned.m16n8k16.row.col.f32.bf16.bf16.f32 "
        "{%0,%1,%2,%3}, {%4,%5,%6,%7}, {%8,%9}, {%0,%1,%2,%3};"
        : "+f"(c[0]), "+f"(c[1]), "+f"(c[2]), "+f"(c[3])
        : "r"(a[0]), "r"(a[1]), "r"(a[2]), "r"(a[3]), "r"(b0), "r"(b1));
}

// ---------------- prep kernels ----------------
// k-space: k 0..255 = h units (Wc rows 64+k), k 256..319 = x dims (Wc rows k-256)
__global__ void wsplit_kernel(const float* __restrict__ Wc, const float* __restrict__ bc) {
    int idx = blockIdx.x * blockDim.x + threadIdx.x;
    if (idx < G4 * 320) {
        int k = idx % 320;
        int gcol = idx / 320;
        int u = gcol >> 2, g = gcol & 3;
        int r = (k < 256) ? (64 + k) : (k - 256);
        float w = Wc[r * G4 + g * Hn + u];
        __nv_bfloat16 s[3];
        split3(w, s[0], s[1], s[2]);
#pragma unroll
        for (int p = 0; p < 3; p++) g_W[p][gcol][k] = s[p];
    }
    if (idx < G4) {
        int u = idx >> 2, g = idx & 3;
        g_br[idx] = bc[g * Hn + u];
    }
}

__global__ void xsplit_kernel(const float* __restrict__ x) {
    int idx = blockIdx.x * blockDim.x + threadIdx.x;
    int d = idx & 63;
    int tt = (idx >> 6) & 511;
    int b = idx >> 15;
    if (b >= Bn) return;
    float v = x[((size_t)b * Tn + tt) * Dn + d];
    __nv_bfloat16 s[3];
    split3(v, s[0], s[1], s[2]);
#pragma unroll
    for (int p = 0; p < 3; p++) g_xT[p][tt][b][d] = s[p];
}

__global__ void init_kernel() {
    int idx = blockIdx.x * blockDim.x + threadIdx.x;
    if (idx < 3 * Bn * Hn / 2)
        ((unsigned*)g_h[0])[idx] = 0u;
    if (idx < 32) g_bar4[idx] = 0;
}

// ---------------- persistent step kernel ----------------
// grid (8, 16): bi = batch slice (128 rows), ci = 16 hidden units (64 gate cols)
__global__ __launch_bounds__(256)
void step_kernel() {
    extern __shared__ char dsm[];
    const uint32_t sbase = smem_u32(dsm);

    const int tid  = threadIdx.x;
    const int lane = tid & 31;
    const int warp = tid >> 5;
    const int p  = warp >> 1;       // pair id: warps {2p, 2p+1} (different SMSPs,
                                    // and each SMSP hosts warps of two pairs)
    const int wn = warp & 1;        // 0/1 within pair (n-half)
    const int ptid = (wn << 5) | lane;      // 0..63 within pair
    const int bi = blockIdx.x;
    const int ci = blockIdx.y;
    const int row0 = bi * 128;
    const int prow0 = row0 + p * 32;        // this pair's global row base

    const uint32_t PA0 = sbase + (uint32_t)(p * 2) * PBUF;
    const uint32_t PA1 = PA0 + PBUF;

#define BARP() asm volatile("bar.sync %0, 64;" :: "r"(1 + p) : "memory")

    // resident B (weights, K=320): 3 planes x 64 cols x 640B, XOR-swizzled (CTA-wide)
#pragma unroll
    for (int i = 0; i < 30; i++) {
        int flat = i * 256 + tid;                 // < 7680
        int q = flat % 40;
        int n = (flat / 40) & 63;
        int pp = flat / 2560;
        uint32_t off = (uint32_t)(q * 16) ^ (uint32_t)((n & 7) << 4);
        cp16(sbase + B_OFF + (uint32_t)(pp * 64 + n) * BPITCH + off,
             (const char*)&g_W[pp][ci * 64 + n][q * 8]);
    }
    cp_commit();

    float cold[8], nold[8];
#pragma unroll
    for (int q = 0; q < 8; q++) { cold[q] = 0.0f; nold[q] = 1.0f; }

    const int mrow = lane & 15;
    const int kAo  = (lane >> 4) << 3;
    const int nBo  = ((lane >> 4) << 3) + (lane & 7);
    const int kBo  = ((lane >> 3) & 1) << 3;
    const bool odd = lane & 1;
    const int jh = (lane >> 1) & 1;

    float cm[2][4][4], cl[2][4][4], cx[2][4][4];

    // one k=64 chunk from pair A buffer abuf + resident B at k-byte offset bko
    auto do_chunk = [&](uint32_t abuf, uint32_t bko) {
#pragma unroll
        for (int ks = 0; ks < 4; ks++) {
            uint32_t a[3][2][4], b[3][2][4];
#pragma unroll
            for (int pp = 0; pp < 3; pp++) {
#pragma unroll
                for (int mi = 0; mi < 2; mi++) {
                    int lr = mi * 16 + mrow;      // 0..31 within pair rows
                    uint32_t off = (uint32_t)((ks * 16 + kAo) * 2) ^ (uint32_t)((lr & 7) << 4);
                    LDSM4(a[pp][mi], abuf + (uint32_t)(pp * 32 + lr) * 128 + off);
                }
#pragma unroll
                for (int pr = 0; pr < 2; pr++) {
                    int brow = wn * 32 + pr * 16 + nBo;
                    uint32_t off = (bko + (uint32_t)((ks * 16 + kBo) * 2)) ^ (uint32_t)((brow & 7) << 4);
                    LDSM4(b[pp][pr], sbase + B_OFF + (uint32_t)(pp * 64 + brow) * BPITCH + off);
                }
            }
#pragma unroll
            for (int mi = 0; mi < 2; mi++)
#pragma unroll
                for (int ni = 0; ni < 4; ni++) {
                    const int pr = ni >> 1, o = (ni & 1) * 2;
                    mma_bf16(cm[mi][ni], a[0][mi], b[0][pr][o], b[0][pr][o+1]); // hi*hi
                    mma_bf16(cl[mi][ni], a[0][mi], b[1][pr][o], b[1][pr][o+1]); // hi*mid
                    mma_bf16(cl[mi][ni], a[1][mi], b[0][pr][o], b[0][pr][o+1]); // mid*hi
                    mma_bf16(cl[mi][ni], a[0][mi], b[2][pr][o], b[2][pr][o+1]); // hi*lo
                    mma_bf16(cl[mi][ni], a[1][mi], b[1][pr][o], b[1][pr][o+1]); // mid*mid
                    mma_bf16(cl[mi][ni], a[2][mi], b[0][pr][o], b[0][pr][o+1]); // lo*hi
                }
        }
    };

    // pair-local h-chunk copy: chunk ch (k = ch*64..) -> buffer (ch&1)
    auto issue_h = [&](int ch, int hbuf) {
        const uint32_t abuf = (ch & 1) ? PA1 : PA0;
#pragma unroll
        for (int i = 0; i < 12; i++) {
            int flat = i * 64 + ptid;             // < 768
            int q = flat & 7;
            int r = (flat >> 3) & 31;
            int pp = flat >> 8;
            uint32_t off = (uint32_t)(q * 16) ^ (uint32_t)((r & 7) << 4);
            cp16(abuf + (uint32_t)(pp * 32 + r) * 128 + off,
                 (const char*)&g_h[hbuf][pp][prow0 + r][ch * 64 + q * 8]);
        }
        cp_commit();
    };

    // pair-local x(t) copy into buffer 1 (k 256..319)
    auto issue_x = [&](int t) {
#pragma unroll
        for (int i = 0; i < 12; i++) {
            int flat = i * 64 + ptid;
            int q = flat & 7;
            int r = (flat >> 3) & 31;
            int pp = flat >> 8;
            uint32_t off = (uint32_t)(q * 16) ^ (uint32_t)((r & 7) << 4);
            cp16(PA1 + (uint32_t)(pp * 32 + r) * 128 + off,
                 (const char*)&g_xT[pp][t][prow0 + r][q * 8]);
        }
        cp_commit();
    };

    // quarter barrier wait: h units [64q, 64q+64) of step t ready
    // (4 producer CTAs x 4 pairs = 16 pair-arrivals per step)
    auto wait_q = [&](int q, int t) {
        const int tgt = 16 * t;
        const int* pc = &g_bar4[bi * 4 + q];
        while (ld_acq(pc) < tgt) { }
    };

    issue_x(0);                                    // pending: {B, x}
    asm volatile("cp.async.wait_group 0;" ::: "memory");
    __syncthreads();                               // B + x(0) visible CTA-wide

    for (int t = 0; t < Tn; t++) {
        const int hbuf = t & 1;
        const bool last = (t == Tn - 1);

#pragma unroll
        for (int mi = 0; mi < 2; mi++)
#pragma unroll
            for (int ni = 0; ni < 4; ni++)
#pragma unroll
                for (int q = 0; q < 4; q++) { cm[mi][ni][q] = 0.0f; cl[mi][ni][q] = 0.0f; }

        // ---- x phase: h0 copy flies during x compute ----
        wait_q(0, t);
        issue_h(0, hbuf);                          // -> PA0
        // pending here: {x(t), h0} at t>0 (x committed last step), {h0} at t=0
        asm volatile("cp.async.wait_group 1;" ::: "memory");   // x(t) retired
        BARP();                                    // pair's x copies visible
        do_chunk(PA1, 512u);                       // x part (k 256..319)

        // collapse x part + bias into cx, reset cm/cl
#pragma unroll
        for (int mi = 0; mi < 2; mi++)
#pragma unroll
            for (int ni = 0; ni < 4; ni++) {
                int col = ci * 64 + wn * 32 + ni * 8 + (lane & 3) * 2;
                float b0 = g_br[col], b1 = g_br[col + 1];
                cx[mi][ni][0] = cm[mi][ni][0] + cl[mi][ni][0] + b0;
                cx[mi][ni][1] = cm[mi][ni][1] + cl[mi][ni][1] + b1;
                cx[mi][ni][2] = cm[mi][ni][2] + cl[mi][ni][2] + b0;
                cx[mi][ni][3] = cm[mi][ni][3] + cl[mi][ni][3] + b1;
#pragma unroll
                for (int q = 0; q < 4; q++) { cm[mi][ni][q] = 0.0f; cl[mi][ni][q] = 0.0f; }
            }

        BARP();                                    // pair done reading PA1 (x)
        wait_q(1, t);
        issue_h(1, hbuf);                          // -> PA1; pending: {h0, h1}

        // ---- h phase: 4 chunks k=64, pair-local ping-pong ----
#pragma unroll 1
        for (int ch = 0; ch < 4; ch++) {
            if (ch == 3) asm volatile("cp.async.wait_group 0;" ::: "memory");
            else         asm volatile("cp.async.wait_group 1;" ::: "memory");
            BARP();

            do_chunk((ch & 1) ? PA1 : PA0, (uint32_t)(ch * 128));

            BARP();                                // pair done reading this buffer
            if (ch == 0)      { wait_q(2, t); issue_h(2, hbuf); }
            else if (ch == 1) { wait_q(3, t); issue_h(3, hbuf); }
        }
        if (!last) issue_x(t + 1);                 // PA1 free (h3 consumed, post-BARP)

        // ---- epilogue: pair-local, Hs staged in PA0 (h2 consumed, fully bar'd) ----
        __nv_bfloat16* Hs = (__nv_bfloat16*)(dsm + (size_t)(p * 2) * PBUF);

#pragma unroll
        for (int mi = 0; mi < 2; mi++)
#pragma unroll
            for (int ni = 0; ni < 4; ni++) {
                float q0 = (cm[mi][ni][0] + cl[mi][ni][0]) + cx[mi][ni][0];
                float q1 = (cm[mi][ni][1] + cl[mi][ni][1]) + cx[mi][ni][1];
                float q2 = (cm[mi][ni][2] + cl[mi][ni][2]) + cx[mi][ni][2];
                float q3 = (cm[mi][ni][3] + cl[mi][ni][3]) + cx[mi][ni][3];
                float s0 = __shfl_xor_sync(0xFFFFFFFFu, q0, 1);
                float s1 = __shfl_xor_sync(0xFFFFFFFFu, q1, 1);
                float s2 = __shfl_xor_sync(0xFFFFFFFFu, q2, 1);
                float s3 = __shfl_xor_sync(0xFFFFFFFFu, q3, 1);

                float gi = odd ? s2 : q0;
                float gf = odd ? s3 : q1;
                float go = odd ? q2 : s0;
                float gz = odd ? q3 : s1;

                const int lr = mi * 16 + (lane >> 2) + (odd ? 8 : 0);   // 0..31
                const int ul = wn * 8 + ni * 2 + jh;                     // 0..15
                const int qi = mi * 4 + ni;

                gi = fminf(fmaxf(gi, -5.0f), 5.0f);
                gf = fminf(fmaxf(gf, -5.0f), 5.0f);
                float iv = __expf(gi);
                float fv = __expf(gf);

                float cv = fv * cold[qi] + iv * (1.0f - 2.0f / (__expf(2.0f * gz) + 1.0f));
                cv = fminf(fmaxf(cv, -1e6f), 1e6f);
                float nv = fv * nold[qi] + iv;
                nv = fminf(fmaxf(nv, 1e-6f), 1e6f);
                cold[qi] = cv;
                nold[qi] = nv;

                float ov = 1.0f / (1.0f + __expf(-go));
                float hv = ov * (cv / nv);
                if (!isfinite(hv)) hv = 0.0f;

                __nv_bfloat16 h1, h2, h3;
                split3(hv, h1, h2, h3);
                Hs[(0 * 32 + lr) * 16 + ul] = h1;
                Hs[(1 * 32 + lr) * 16 + ul] = h2;
                Hs[(2 * 32 + lr) * 16 + ul] = h3;
                if (last) g_hfull[(prow0 + lr) * Hn + ci * 16 + ul] = hv;
            }
        BARP();                                    // Hs complete within pair

        if (!last) {
            const int nbuf = hbuf ^ 1;
#pragma unroll
            for (int i = 0; i < 3; i++) {
                int flat = i * 64 + ptid;          // < 192
                int q = flat & 1;
                int r = (flat >> 1) & 31;
                int pp = flat >> 6;
                uint4 v = *(const uint4*)&Hs[(pp * 32 + r) * 16 + q * 8];
                *(uint4*)&g_h[nbuf][pp][prow0 + r][ci * 16 + q * 8] = v;
            }
            __threadfence();
            BARP();                                // pair writes done & visible
            if (ptid == 0) atomicAdd(&g_bar4[bi * 4 + (ci >> 2)], 1);
        }
    }
#undef BARP
}

// ---------------- heads ----------------
__global__ void heads1_kernel(const float* __restrict__ Wa1, const float* __restrict__ ba1,
                              const float* __restrict__ Wv1, const float* __restrict__ bv1) {
    int idx = blockIdx.x * blockDim.x + threadIdx.x;
    if (idx >= Bn * 128) return;
    int b = idx >> 7;
    int j = idx & 127;
    const float* hrow = g_hfull + b * Hn;
    if (j < MIDn) {
        float s = ba1[j];
#pragma unroll 8
        for (int k = 0; k < Hn; k++) s = fmaf(hrow[k], Wa1[k * MIDn + j], s);
        g_a1[b * MIDn + j] = fmaxf(s, 0.0f);
    } else {
        int jj = j - MIDn;
        float s = bv1[jj];
#pragma unroll 8
        for (int k = 0; k < Hn; k++) s = fmaf(hrow[k], Wv1[k * MIDn + jj], s);
        g_v1[b * MIDn + jj] = fmaxf(s, 0.0f);
    }
}

__global__ void heads2_kernel(const float* __restrict__ Wa2, const float* __restrict__ ba2,
                              const float* __restrict__ Wv2, const float* __restrict__ bv2,
                              float* __restrict__ out) {
    int b = blockIdx.x * blockDim.x + threadIdx.x;
    if (b >= Bn) return;
    float l0 = ba2[0], l1 = ba2[1], l2 = ba2[2];
#pragma unroll 8
    for (int m = 0; m < MIDn; m++) {
        float a = g_a1[b * MIDn + m];
        l0 = fmaf(a, Wa2[m * An + 0], l0);
        l1 = fmaf(a, Wa2[m * An + 1], l1);
        l2 = fmaf(a, Wa2[m * An + 2], l2);
    }
    float mx = fmaxf(l0, fmaxf(l1, l2));
    float e0 = expf(l0 - mx), e1 = expf(l1 - mx), e2 = expf(l2 - mx);
    float s = e0 + e1 + e2;
    out[b * An + 0] = e0 / s;
    out[b * An + 1] = e1 / s;
    out[b * An + 2] = e2 / s;

    float v = bv2[0];
#pragma unroll 8
    for (int m = 0; m < MIDn; m++) v = fmaf(g_v1[b * MIDn + m], Wv2[m], v);
    out[Bn * An + b] = v;
}

// ---------------- launch ----------------
extern "C" void kernel_launch(void* const* d_in, const int* in_sizes, int n_in,
                              void* d_out, int out_size) {
    const float* x   = (const float*)d_in[0];
    const float* Wc  = (const float*)d_in[1];
    const float* bc  = (const float*)d_in[2];
    const float* Wa1 = (const float*)d_in[3];
    const float* ba1 = (const float*)d_in[4];
    const float* Wa2 = (const float*)d_in[5];
    const float* ba2 = (const float*)d_in[6];
    const float* Wv1 = (const float*)d_in[7];
    const float* bv1 = (const float*)d_in[8];
    const float* Wv2 = (const float*)d_in[9];
    const float* bv2 = (const float*)d_in[10];
    float* out = (float*)d_out;

    cudaFuncSetAttribute(step_kernel, cudaFuncAttributeMaxDynamicSharedMemorySize, SMEM_TOT);

    wsplit_kernel<<<(G4 * 320 + 255) / 256, 256>>>(Wc, bc);
    xsplit_kernel<<<(Bn * Tn * Dn + 255) / 256, 256>>>(x);
    init_kernel<<<(3 * Bn * Hn / 2 + 255) / 256, 256>>>();

    step_kernel<<<dim3(8, 16), 256, SMEM_TOT>>>();

    heads1_kernel<<<(Bn * 128 + 255) / 256, 256>>>(Wa1, ba1, Wv1, bv1);
    heads2_kernel<<<(Bn + 255) / 256, 256>>>(Wa2, ba2, Wv2, bv2, out);
}